// round 3
// baseline (speedup 1.0000x reference)
#include <cuda_runtime.h>
#include <math.h>

typedef unsigned long long ull;

// ---------------------------------------------------------------------------
// f32x2 packed-FMA helpers (sm_100+ PTX; ptxas never emits these from C++)
// ---------------------------------------------------------------------------
__device__ __forceinline__ ull pack2(float lo, float hi) {
    ull v;
    asm("mov.b64 %0, {%1, %2};" : "=l"(v) : "f"(lo), "f"(hi));
    return v;
}
__device__ __forceinline__ void unpack2(ull v, float& lo, float& hi) {
    asm("mov.b64 {%0, %1}, %2;" : "=f"(lo), "=f"(hi) : "l"(v));
}
__device__ __forceinline__ void ffma2(ull& d, ull a, ull b) {
    asm("fma.rn.f32x2 %0, %1, %2, %0;" : "+l"(d) : "l"(a), "l"(b));
}

// ---------------------------------------------------------------------------
// Scratch (no allocations allowed -> static __device__ arrays)
// ---------------------------------------------------------------------------
__device__ float g_h1[256 * 3 * 50625];  // [B,3,15,15,15,15]
__device__ float g_h2[256 * 3 * 20736];  // [B,3,12,12,12,12]
__device__ float g_h3[256 * 4 * 6561];   // [B,4,9,9,9,9]
__device__ float g_h4[256 * 5 * 1296];   // [B,5,6,6,6,6]
__device__ float g_h5[256 * 5 * 256];    // [B,5,4,4,4,4] == [B,1280]

// ---------------------------------------------------------------------------
// 4D conv + bias + relu, f32x2 packed math.
//   in : [B, CIN, S, S, S, S]; w: [COUT, CIN, K,K,K,K]; out: [B,COUT,T,T,T,T]
// Block = NS slices, slice = one (b, ow). Per ci: stage NS input slabs into
// smem (z-row stride RS odd -> conflict-free). Thread = (slice, ox, oy),
// accumulates COUT x T outputs packed as oz-pairs in 64-bit registers.
// Odd T: padded pair lane reads slab's RS-padding slot; result discarded.
// ---------------------------------------------------------------------------
template <int S, int K, int CIN, int COUT, int NS, int BLK, int MINB, bool WDUP>
__global__ void __launch_bounds__(BLK, MINB)
conv4d_relu_f2(const float* __restrict__ x,
               const float* __restrict__ w,
               const float* __restrict__ bias,
               float* __restrict__ y)
{
    constexpr int T    = S - K + 1;
    constexpr int P    = (T + 1) / 2;          // oz pairs (incl. pad lane)
    constexpr int RS   = (S & 1) ? S : S + 1;  // padded z-row stride (odd)
    constexpr int S3   = S * S * S;
    constexpr int SLAB = K * S * S * RS;       // floats per slice slab
    constexpr int WN   = COUT * CIN * K * K * K * K;
    constexpr int NR   = S + (T & 1);          // row scalars to read
    constexpr int NE   = P + (K - 1) / 2;      // aligned pairs needed
    constexpr int NO   = P + (K - 2) / 2;      // shifted pairs needed

    extern __shared__ float sm[];
    float* slab0 = sm + (WDUP ? 2 * WN : WN);

    const int tid = threadIdx.x;

    // stage weights (optionally pre-duplicated for direct LDS.64 broadcast)
    if (WDUP) {
        float2* wd = reinterpret_cast<float2*>(sm);
        for (int i = tid; i < WN; i += BLK) {
            float v = w[i];
            wd[i] = make_float2(v, v);
        }
    } else {
        for (int i = tid; i < WN; i += BLK) sm[i] = w[i];
    }

    const int slice0 = blockIdx.x * NS;
    const int s  = tid / (T * T);
    const int rr = tid - s * (T * T);
    const int ox = rr / T;
    const int oy = rr - ox * T;
    const bool active = (tid < NS * T * T);
    const int b_t  = (slice0 + s) / T;   // this thread's batch
    const int ow_t = (slice0 + s) % T;   // this thread's ow
    float* slab = slab0 + s * SLAB;

    ull acc[COUT][P];
#pragma unroll
    for (int co = 0; co < COUT; ++co)
#pragma unroll
        for (int p = 0; p < P; ++p) acc[co][p] = 0ull;

    for (int ci = 0; ci < CIN; ++ci) {
        __syncthreads();   // protect slabs from previous iteration's readers
        for (int i = tid; i < NS * K * S3; i += BLK) {
            int ss = i / (K * S3);
            int r  = i - ss * (K * S3);
            int sl = slice0 + ss;
            int bb = sl / T, oww = sl % T;
            int kw = r / S3;
            int r1 = r - kw * S3;
            int xx = r1 / (S * S);
            int r2 = r1 - xx * (S * S);
            int yy = r2 / S;
            int zz = r2 - yy * S;
            slab0[ss * SLAB + ((kw * S + xx) * S + yy) * RS + zz] =
                x[((size_t)(bb * CIN + ci) * S + oww) * S3 + r];
        }
        __syncthreads();

        if (active) {
#pragma unroll 1
            for (int kw = 0; kw < K; ++kw)
#pragma unroll 1
            for (int kx = 0; kx < K; ++kx)
#pragma unroll 1
            for (int ky = 0; ky < K; ++ky) {
                const float* row = &slab[((kw * S + ox + kx) * S + oy + ky) * RS];
                float r[NR];
#pragma unroll
                for (int z = 0; z < NR; ++z) r[z] = row[z];

                ull e[NE], o[NO];
#pragma unroll
                for (int i = 0; i < NE; ++i) e[i] = pack2(r[2 * i], r[2 * i + 1]);
#pragma unroll
                for (int i = 0; i < NO; ++i) o[i] = pack2(r[2 * i + 1], r[2 * i + 2]);

                ull wp[COUT][K];
#pragma unroll
                for (int co = 0; co < COUT; ++co)
#pragma unroll
                    for (int kz = 0; kz < K; ++kz) {
                        int wi = ((((co * CIN + ci) * K + kw) * K + kx) * K + ky) * K + kz;
                        if (WDUP) {
                            wp[co][kz] = reinterpret_cast<const ull*>(sm)[wi];
                        } else {
                            float wv = sm[wi];
                            wp[co][kz] = pack2(wv, wv);
                        }
                    }

#pragma unroll
                for (int p = 0; p < P; ++p)
#pragma unroll
                    for (int co = 0; co < COUT; ++co)
#pragma unroll
                        for (int kz = 0; kz < K; ++kz) {
                            ull a = ((kz & 1) == 0) ? e[p + kz / 2] : o[p + kz / 2];
                            ffma2(acc[co][p], a, wp[co][kz]);
                        }
            }
        }
    }

    if (active) {
#pragma unroll
        for (int co = 0; co < COUT; ++co) {
            float bv = bias[co];
            float* yb = y + (((((size_t)b_t * COUT + co) * T + ow_t) * T + ox) * T + oy) * T;
#pragma unroll
            for (int p = 0; p < P; ++p) {
                float lo, hi;
                unpack2(acc[co][p], lo, hi);
                float vlo = lo + bv;
                yb[2 * p] = vlo > 0.f ? vlo : 0.f;
                if (2 * p + 1 < T) {
                    float vhi = hi + bv;
                    yb[2 * p + 1] = vhi > 0.f ? vhi : 0.f;
                }
            }
        }
    }
}

// ---------------------------------------------------------------------------
// Dense head: relu(h @ dw1.T + db1) @ dw2.T + db2 -> softmax over 2 classes.
// ---------------------------------------------------------------------------
__global__ void dense_head(const float* __restrict__ h,
                           const float* __restrict__ dw1,
                           const float* __restrict__ db1,
                           const float* __restrict__ dw2,
                           const float* __restrict__ db2,
                           float* __restrict__ out)
{
    __shared__ float hb[1280];
    __shared__ float a[33];
    const int b   = blockIdx.x;
    const int tid = threadIdx.x;

    for (int i = tid; i < 1280; i += blockDim.x) hb[i] = h[b * 1280 + i];
    __syncthreads();

    const int warp = tid >> 5, lane = tid & 31;
    const int nwarps = blockDim.x >> 5;
    for (int co = warp; co < 33; co += nwarps) {
        float s = 0.f;
        for (int i = lane; i < 1280; i += 32) s += hb[i] * dw1[co * 1280 + i];
#pragma unroll
        for (int o = 16; o > 0; o >>= 1) s += __shfl_down_sync(0xffffffffu, s, o);
        if (lane == 0) {
            float v = s + db1[co];
            a[co] = v > 0.f ? v : 0.f;
        }
    }
    __syncthreads();

    if (tid == 0) {
        float z0 = db2[0], z1 = db2[1];
#pragma unroll
        for (int i = 0; i < 33; ++i) {
            z0 += a[i] * dw2[i];
            z1 += a[i] * dw2[33 + i];
        }
        float m  = fmaxf(z0, z1);
        float e0 = expf(z0 - m), e1 = expf(z1 - m);
        float inv = 1.f / (e0 + e1);
        out[2 * b]     = e0 * inv;
        out[2 * b + 1] = e1 * inv;
    }
}

// ---------------------------------------------------------------------------
// Launch
// ---------------------------------------------------------------------------
extern "C" void kernel_launch(void* const* d_in, const int* in_sizes, int n_in,
                              void* d_out, int out_size)
{
    const float* x   = (const float*)d_in[0];
    const float* w1  = (const float*)d_in[1];
    const float* b1  = (const float*)d_in[2];
    const float* w2  = (const float*)d_in[3];
    const float* b2  = (const float*)d_in[4];
    const float* w3  = (const float*)d_in[5];
    const float* b3  = (const float*)d_in[6];
    const float* w4  = (const float*)d_in[7];
    const float* b4  = (const float*)d_in[8];
    const float* w5  = (const float*)d_in[9];
    const float* b5  = (const float*)d_in[10];
    const float* dw1 = (const float*)d_in[11];
    const float* db1 = (const float*)d_in[12];
    const float* dw2 = (const float*)d_in[13];
    const float* db2 = (const float*)d_in[14];
    float* out = (float*)d_out;

    float *h1, *h2, *h3, *h4, *h5;
    cudaGetSymbolAddress((void**)&h1, g_h1);
    cudaGetSymbolAddress((void**)&h2, g_h2);
    cudaGetSymbolAddress((void**)&h3, g_h3);
    cudaGetSymbolAddress((void**)&h4, g_h4);
    cudaGetSymbolAddress((void**)&h5, g_h5);

    // L1: S=18 K=4 CIN=1 COUT=3  NS=1 BLK=256 MINB=2 WDUP
    //   smem = 2*768*4 + 24624*4 = 104,640 B   (2 blocks/SM)
    // L2: S=15 K=4 CIN=3 COUT=3  NS=1 BLK=160 MINB=3 WDUP
    //   smem = 2*2304*4 + 13500*4 = 72,432 B   (3 blocks/SM)
    // L3: S=12 K=4 CIN=3 COUT=4  NS=3 BLK=256 MINB=2 no-WDUP
    //   smem = 3072*4 + 3*7488*4 = 102,144 B   (2 blocks/SM)
    // L4: S=9  K=4 CIN=4 COUT=5  NS=4 BLK=160 MINB=2 WDUP
    //   smem = 2*5120*4 + 4*2916*4 = 87,616 B  (2 blocks/SM)
    // L5: S=6  K=3 CIN=5 COUT=5  NS=4 BLK=64  MINB=8 WDUP
    //   smem = 2*2025*4 + 4*756*4 = 28,296 B
    constexpr int sm1 = 2 * 768 * 4  + 4 * 18 * 18 * 19 * 4;
    constexpr int sm2 = 2 * 2304 * 4 + 4 * 15 * 15 * 15 * 4;
    constexpr int sm3 = 3072 * 4     + 3 * 4 * 12 * 12 * 13 * 4;
    constexpr int sm4 = 2 * 5120 * 4 + 4 * 4 * 9 * 9 * 9 * 4;
    constexpr int sm5 = 2 * 2025 * 4 + 4 * 3 * 6 * 6 * 7 * 4;

    cudaFuncSetAttribute((conv4d_relu_f2<18, 4, 1, 3, 1, 256, 2, true>),
                         cudaFuncAttributeMaxDynamicSharedMemorySize, sm1);
    cudaFuncSetAttribute((conv4d_relu_f2<15, 4, 3, 3, 1, 160, 3, true>),
                         cudaFuncAttributeMaxDynamicSharedMemorySize, sm2);
    cudaFuncSetAttribute((conv4d_relu_f2<12, 4, 3, 4, 3, 256, 2, false>),
                         cudaFuncAttributeMaxDynamicSharedMemorySize, sm3);
    cudaFuncSetAttribute((conv4d_relu_f2<9, 4, 4, 5, 4, 160, 2, true>),
                         cudaFuncAttributeMaxDynamicSharedMemorySize, sm4);
    cudaFuncSetAttribute((conv4d_relu_f2<6, 3, 5, 5, 4, 64, 8, true>),
                         cudaFuncAttributeMaxDynamicSharedMemorySize, sm5);

    conv4d_relu_f2<18, 4, 1, 3, 1, 256, 2, true ><<<256 * 15,     256, sm1>>>(x,  w1, b1, h1);
    conv4d_relu_f2<15, 4, 3, 3, 1, 160, 3, true ><<<256 * 12,     160, sm2>>>(h1, w2, b2, h2);
    conv4d_relu_f2<12, 4, 3, 4, 3, 256, 2, false><<<256 * 9 / 3,  256, sm3>>>(h2, w3, b3, h3);
    conv4d_relu_f2< 9, 4, 4, 5, 4, 160, 2, true ><<<256 * 6 / 4,  160, sm4>>>(h3, w4, b4, h4);
    conv4d_relu_f2< 6, 3, 5, 5, 4,  64, 8, true ><<<256 * 4 / 4,   64, sm5>>>(h4, w5, b5, h5);
    dense_head<<<256, 256>>>(h5, dw1, db1, dw2, db2, out);
}

// round 4
// speedup vs baseline: 1.1138x; 1.1138x over previous
#include <cuda_runtime.h>
#include <math.h>

typedef unsigned long long ull;

// ---------------------------------------------------------------------------
// f32x2 packed-FMA helpers (sm_100+; ptxas never emits FFMA2 from C++)
// ---------------------------------------------------------------------------
__device__ __forceinline__ ull pack2(float lo, float hi) {
    ull v;
    asm("mov.b64 %0, {%1, %2};" : "=l"(v) : "f"(lo), "f"(hi));
    return v;
}
__device__ __forceinline__ void unpack2(ull v, float& lo, float& hi) {
    asm("mov.b64 {%0, %1}, %2;" : "=f"(lo), "=f"(hi) : "l"(v));
}
__device__ __forceinline__ void ffma2(ull& d, ull a, ull b) {
    asm("fma.rn.f32x2 %0, %1, %2, %0;" : "+l"(d) : "l"(a), "l"(b));
}

// ---------------------------------------------------------------------------
// Scratch (no allocations allowed -> static __device__ arrays)
// ---------------------------------------------------------------------------
__device__ float g_h1[256 * 3 * 50625];  // [B,3,15,15,15,15]
__device__ float g_h2[256 * 3 * 20736];  // [B,3,12,12,12,12]
__device__ float g_h3[256 * 4 * 6561];   // [B,4,9,9,9,9]
__device__ float g_h4[256 * 5 * 1296];   // [B,5,6,6,6,6]
__device__ float g_h5[256 * 5 * 256];    // [B,5,4,4,4,4] == [B,1280]

// ---------------------------------------------------------------------------
// 4D conv + bias + relu, f32x2 packed math, registers budgeted.
//   in : [B,CIN,S,S,S,S]; w: [COUT,CIN,K,K,K,K]; out: [B,COUT,T,T,T,T]
// Block = NS slices of (b,ow). Each slice's oz range is split ZSPL ways.
// Thread = (slice, z-chunk, ox, oy); accumulates COUT x P oz-pairs in ull.
// Weights pre-duplicated in smem as (w,w) pairs -> one LDS.64 per FFMA2 operand,
// loaded transiently per (row, co) to cap live registers.
// ---------------------------------------------------------------------------
template <int S, int K, int CIN, int COUT, int ZSPL, int NS, int BLK, int MINB>
__global__ void __launch_bounds__(BLK, MINB)
conv4d_relu_f2(const float* __restrict__ x,
               const float* __restrict__ w,
               const float* __restrict__ bias,
               float* __restrict__ y)
{
    constexpr int T    = S - K + 1;
    constexpr int OZB  = (T + ZSPL - 1) / ZSPL;    // oz per chunk
    constexpr int P    = (OZB + 1) / 2;            // packed pairs per chunk
    constexpr int RS   = (S & 1) ? S : S + 1;      // padded z-row stride (odd)
    constexpr int S3   = S * S * S;
    constexpr int SLAB = K * S * S * RS;
    constexpr int WN   = COUT * CIN * K * K * K * K;
    constexpr int NE   = P + (K - 1) / 2;          // aligned pairs
    constexpr int NO   = P + (K - 2) / 2;          // shifted pairs
    constexpr int NR   = (2 * NE > 2 * NO + 1) ? 2 * NE : 2 * NO + 1;

    extern __shared__ float sm[];
    ull*   swu   = reinterpret_cast<ull*>(sm);     // [WN] duplicated weights
    float* slab0 = sm + 2 * WN;

    const int tid = threadIdx.x;

    {   // stage duplicated weights
        float2* wd = reinterpret_cast<float2*>(sm);
        for (int i = tid; i < WN; i += BLK) {
            float v = w[i];
            wd[i] = make_float2(v, v);
        }
    }

    constexpr int TT = T * T;
    constexpr int PERS = ZSPL * TT;
    const int s   = tid / PERS;
    const int r0  = tid - s * PERS;
    const int zc  = r0 / TT;
    const int rr  = r0 - zc * TT;
    const int ox  = rr / T;
    const int oy  = rr - ox * T;
    const bool active = (tid < NS * PERS);
    const int slice = blockIdx.x * NS + s;
    const int b_t   = slice / T;
    const int ow_t  = slice % T;
    const int oz0   = zc * OZB;
    float* slab = slab0 + s * SLAB;

    ull acc[COUT][P];
#pragma unroll
    for (int co = 0; co < COUT; ++co)
#pragma unroll
        for (int p = 0; p < P; ++p) acc[co][p] = 0ull;

    for (int ci = 0; ci < CIN; ++ci) {
        __syncthreads();   // protect slabs from previous iteration's readers
        for (int i = tid; i < NS * K * S3; i += BLK) {
            int ss = i / (K * S3);
            int r  = i - ss * (K * S3);
            int sl = blockIdx.x * NS + ss;
            int bb = sl / T, oww = sl % T;
            int kw = r / S3;
            int r1 = r - kw * S3;
            int xx = r1 / (S * S);
            int r2 = r1 - xx * (S * S);
            int yy = r2 / S;
            int zz = r2 - yy * S;
            slab0[ss * SLAB + ((kw * S + xx) * S + yy) * RS + zz] =
                x[((size_t)(bb * CIN + ci) * S + oww) * S3 + r];
        }
        __syncthreads();

        if (active) {
#pragma unroll 1
            for (int kw = 0; kw < K; ++kw)
#pragma unroll 1
            for (int kx = 0; kx < K; ++kx)
#pragma unroll 1
            for (int ky = 0; ky < K; ++ky) {
                const float* row =
                    &slab[((kw * S + ox + kx) * S + oy + ky) * RS + oz0];
                float r[NR];
#pragma unroll
                for (int z = 0; z < NR; ++z) r[z] = row[z];

                ull e[NE], o[NO];
#pragma unroll
                for (int i = 0; i < NE; ++i) e[i] = pack2(r[2 * i], r[2 * i + 1]);
#pragma unroll
                for (int i = 0; i < NO; ++i) o[i] = pack2(r[2 * i + 1], r[2 * i + 2]);

#pragma unroll
                for (int co = 0; co < COUT; ++co) {
                    ull wp[K];
#pragma unroll
                    for (int kz = 0; kz < K; ++kz)
                        wp[kz] = swu[((((co * CIN + ci) * K + kw) * K + kx) * K + ky) * K + kz];
#pragma unroll
                    for (int p = 0; p < P; ++p)
#pragma unroll
                        for (int kz = 0; kz < K; ++kz) {
                            ull a = ((kz & 1) == 0) ? e[p + kz / 2] : o[p + kz / 2];
                            ffma2(acc[co][p], a, wp[kz]);
                        }
                }
            }
        }
    }

    if (active) {
#pragma unroll
        for (int co = 0; co < COUT; ++co) {
            float bv = bias[co];
            float* yb = y + (((((size_t)b_t * COUT + co) * T + ow_t) * T + ox) * T + oy) * T + oz0;
#pragma unroll
            for (int p = 0; p < P; ++p) {
                float lo, hi;
                unpack2(acc[co][p], lo, hi);
                if (oz0 + 2 * p < T) {
                    float vlo = lo + bv;
                    yb[2 * p] = vlo > 0.f ? vlo : 0.f;
                }
                if (oz0 + 2 * p + 1 < T) {
                    float vhi = hi + bv;
                    yb[2 * p + 1] = vhi > 0.f ? vhi : 0.f;
                }
            }
        }
    }
}

// ---------------------------------------------------------------------------
// Dense head: relu(h @ dw1.T + db1) @ dw2.T + db2 -> softmax over 2 classes.
// ---------------------------------------------------------------------------
__global__ void dense_head(const float* __restrict__ h,
                           const float* __restrict__ dw1,
                           const float* __restrict__ db1,
                           const float* __restrict__ dw2,
                           const float* __restrict__ db2,
                           float* __restrict__ out)
{
    __shared__ float hb[1280];
    __shared__ float a[33];
    const int b   = blockIdx.x;
    const int tid = threadIdx.x;

    for (int i = tid; i < 1280; i += blockDim.x) hb[i] = h[b * 1280 + i];
    __syncthreads();

    const int warp = tid >> 5, lane = tid & 31;
    const int nwarps = blockDim.x >> 5;
    for (int co = warp; co < 33; co += nwarps) {
        float s = 0.f;
        for (int i = lane; i < 1280; i += 32) s += hb[i] * dw1[co * 1280 + i];
#pragma unroll
        for (int o = 16; o > 0; o >>= 1) s += __shfl_down_sync(0xffffffffu, s, o);
        if (lane == 0) {
            float v = s + db1[co];
            a[co] = v > 0.f ? v : 0.f;
        }
    }
    __syncthreads();

    if (tid == 0) {
        float z0 = db2[0], z1 = db2[1];
#pragma unroll
        for (int i = 0; i < 33; ++i) {
            z0 += a[i] * dw2[i];
            z1 += a[i] * dw2[33 + i];
        }
        float m  = fmaxf(z0, z1);
        float e0 = expf(z0 - m), e1 = expf(z1 - m);
        float inv = 1.f / (e0 + e1);
        out[2 * b]     = e0 * inv;
        out[2 * b + 1] = e1 * inv;
    }
}

// ---------------------------------------------------------------------------
// Launch
// ---------------------------------------------------------------------------
extern "C" void kernel_launch(void* const* d_in, const int* in_sizes, int n_in,
                              void* d_out, int out_size)
{
    const float* x   = (const float*)d_in[0];
    const float* w1  = (const float*)d_in[1];
    const float* b1  = (const float*)d_in[2];
    const float* w2  = (const float*)d_in[3];
    const float* b2  = (const float*)d_in[4];
    const float* w3  = (const float*)d_in[5];
    const float* b3  = (const float*)d_in[6];
    const float* w4  = (const float*)d_in[7];
    const float* b4  = (const float*)d_in[8];
    const float* w5  = (const float*)d_in[9];
    const float* b5  = (const float*)d_in[10];
    const float* dw1 = (const float*)d_in[11];
    const float* db1 = (const float*)d_in[12];
    const float* dw2 = (const float*)d_in[13];
    const float* db2 = (const float*)d_in[14];
    float* out = (float*)d_out;

    float *h1, *h2, *h3, *h4, *h5;
    cudaGetSymbolAddress((void**)&h1, g_h1);
    cudaGetSymbolAddress((void**)&h2, g_h2);
    cudaGetSymbolAddress((void**)&h3, g_h3);
    cudaGetSymbolAddress((void**)&h4, g_h4);
    cudaGetSymbolAddress((void**)&h5, g_h5);

    // L1: ZSPL=2 NS=1 BLK=480 (450 active)  smem=2*768f + 24624f = 104,640B -> 2 blk/SM, 30 warps
    // L2: ZSPL=2 NS=1 BLK=288 (288 active)  smem=2*2304f + 13500f = 72,432B -> 3 blk/SM, 27 warps
    // L3: ZSPL=1 NS=3 BLK=256 (243 active)  smem=2*3072f + 3*7488f = 114,432B -> 2 blk/SM
    // L4: ZSPL=1 NS=6 BLK=224 (216 active)  smem=2*5120f + 6*2916f = 110,944B -> 2 blk/SM
    // L5: ZSPL=1 NS=8 BLK=128 (128 active)  smem=2*2025f + 8*756f  =  40,392B
    constexpr int sm1 = (2 * 768  + 1 * 24624) * 4;
    constexpr int sm2 = (2 * 2304 + 1 * 13500) * 4;
    constexpr int sm3 = (2 * 3072 + 3 * 7488) * 4;
    constexpr int sm4 = (2 * 5120 + 6 * 2916) * 4;
    constexpr int sm5 = (2 * 2025 + 8 * 756) * 4;

    cudaFuncSetAttribute((conv4d_relu_f2<18, 4, 1, 3, 2, 1, 480, 2>),
                         cudaFuncAttributeMaxDynamicSharedMemorySize, sm1);
    cudaFuncSetAttribute((conv4d_relu_f2<15, 4, 3, 3, 2, 1, 288, 3>),
                         cudaFuncAttributeMaxDynamicSharedMemorySize, sm2);
    cudaFuncSetAttribute((conv4d_relu_f2<12, 4, 3, 4, 1, 3, 256, 2>),
                         cudaFuncAttributeMaxDynamicSharedMemorySize, sm3);
    cudaFuncSetAttribute((conv4d_relu_f2<9, 4, 4, 5, 1, 6, 224, 2>),
                         cudaFuncAttributeMaxDynamicSharedMemorySize, sm4);
    cudaFuncSetAttribute((conv4d_relu_f2<6, 3, 5, 5, 1, 8, 128, 4>),
                         cudaFuncAttributeMaxDynamicSharedMemorySize, sm5);

    conv4d_relu_f2<18, 4, 1, 3, 2, 1, 480, 2><<<256 * 15,     480, sm1>>>(x,  w1, b1, h1);
    conv4d_relu_f2<15, 4, 3, 3, 2, 1, 288, 3><<<256 * 12,     288, sm2>>>(h1, w2, b2, h2);
    conv4d_relu_f2<12, 4, 3, 4, 1, 3, 256, 2><<<256 * 9 / 3,  256, sm3>>>(h2, w3, b3, h3);
    conv4d_relu_f2< 9, 4, 4, 5, 1, 6, 224, 2><<<256 * 6 / 6,  224, sm4>>>(h3, w4, b4, h4);
    conv4d_relu_f2< 6, 3, 5, 5, 1, 8, 128, 4><<<256 * 4 / 8,  128, sm5>>>(h4, w5, b5, h5);
    dense_head<<<256, 256>>>(h5, dw1, db1, dw2, db2, out);
}